// round 9
// baseline (speedup 1.0000x reference)
#include <cuda_runtime.h>
#include <cstdint>

// VoxelHashTable — single fused persistent kernel.
// R8 evidence: the 3 pre-pass kernels + launch gaps cost ~31us while their
// actual work is <8us -> per-launch overhead dominates. Fuse hash, scan,
// scatter, and a persistent gather into ONE launch with software grid
// barriers (all 592 blocks co-resident by construction: 4 blocks/SM via
// __launch_bounds__(256,4), 592 <= 4*148).
//
// Phases (grid barrier between each):
//  1. hash queries -> vidx, rank-in-bin (atomicAdd return)
//  2. block 0: 8192-bin exclusive scan -> g_off; re-zero g_hist for replay
//  3. atomic-free scatter: perm[off[bin]+rank] = qi
//  4. persistent gather over sorted order: warp-per-row, 6 float4 loads
//     (MLP=6), __stcs stores; instantaneous window ~4.7k sorted rows -> L2
//     dedups duplicate feature rows.

#define FEATURE_DIM 768
#define VEC4_PER_ROW (FEATURE_DIM / 4)     // 192
#define V4_PER_LANE (VEC4_PER_ROW / 32)    // 6
#define TABLE_MASK ((1u << 20) - 1u)
#define M_MAX (1 << 18)                    // 262144 queries
#define BUCKET_SHIFT 7                     // 128 voxel rows per bucket
#define NBINS 8192
#define NBLOCKS 592                        // 4 * 148 (residency-safe on 148/152 SM)
#define NTHREADS 256

__device__ int g_vidx[M_MAX];
__device__ int g_rank[M_MAX];
__device__ int g_perm[M_MAX];
__device__ int g_hist[NBINS];              // zero at load; phase 2 re-zeroes
__device__ int g_off[NBINS];
__device__ unsigned g_bar_count;           // self-resetting
__device__ unsigned g_bar_gen;             // monotonic across replays

__device__ __forceinline__ void grid_barrier()
{
    __syncthreads();
    if (threadIdx.x == 0) {
        __threadfence();                       // publish this block's writes
        const unsigned gen = *(volatile unsigned*)&g_bar_gen;
        if (atomicAdd(&g_bar_count, 1) == gridDim.x - 1) {
            g_bar_count = 0;                   // reset BEFORE release
            __threadfence();
            *(volatile unsigned*)&g_bar_gen = gen + 1;   // release
        } else {
            while (*(volatile unsigned*)&g_bar_gen == gen)
                __nanosleep(64);
        }
        __threadfence();                       // acquire
    }
    __syncthreads();
}

__global__ void __launch_bounds__(NTHREADS, 4) voxel_fused(
    const float* __restrict__ query_pts,        // [M, 3]
    const float4* __restrict__ voxel_features,  // [total_voxels, 192] as float4
    const int* __restrict__ buf,                // [2^20], int32
    float4* __restrict__ out,                   // [M, 192] as float4
    int M, int total_voxels)
{
    const int tid  = threadIdx.x;
    const int gtid = blockIdx.x * NTHREADS + tid;
    const int T    = gridDim.x * NTHREADS;      // 151552 threads

    // ---- Phase 1: hash + table lookup + bin rank ----
    for (int qi = gtid; qi < M; qi += T) {
        const float px = __ldg(&query_pts[qi * 3 + 0]);
        const float py = __ldg(&query_pts[qi * 3 + 1]);
        const float pz = __ldg(&query_pts[qi * 3 + 2]);

        // f32 division by 0.1f required for bit-exact floor(q / RES).
        const long long gx = (long long)floorf(px / 0.1f);
        const long long gy = (long long)floorf(py / 0.1f);
        const long long gz = (long long)floorf(pz / 0.1f);

        // Products ~1e10 overflow int32 -> 64-bit. Pow2 mod == AND (neg-safe).
        const unsigned h = (unsigned)((gx * 73856093LL + gy * 19349669LL
                                       + gz * 83492791LL) & (long long)TABLE_MASK);

        int v = __ldg(&buf[h]);
        if (v >= total_voxels) v = -1;

        const int bin = (v >= 0) ? (v >> BUCKET_SHIFT) : (NBINS - 1);
        g_vidx[qi] = v;
        g_rank[qi] = atomicAdd(&g_hist[bin], 1);
    }

    grid_barrier();

    // ---- Phase 2: exclusive scan of 8192 bins (block 0 only) ----
    if (blockIdx.x == 0) {
        constexpr int BPT = NBINS / NTHREADS;   // 32 bins/thread
        const int lane = tid & 31, warp = tid >> 5;

        int sum = 0;
        #pragma unroll 8
        for (int i = 0; i < BPT; i++)
            sum += g_hist[tid * BPT + i];

        int x = sum;                            // inclusive warp scan
        #pragma unroll
        for (int d = 1; d < 32; d <<= 1) {
            int y = __shfl_up_sync(0xFFFFFFFFu, x, d);
            if (lane >= d) x += y;
        }

        __shared__ int ws[NTHREADS / 32];       // 8 warp sums
        if (lane == 31) ws[warp] = x;
        __syncthreads();
        if (tid == 0) {
            int a = 0;
            #pragma unroll
            for (int j = 0; j < NTHREADS / 32; j++) {
                int t = ws[j]; ws[j] = a; a += t;
            }
        }
        __syncthreads();

        int excl = x - sum + ws[warp];
        #pragma unroll 8
        for (int i = 0; i < BPT; i++) {
            const int b = tid * BPT + i;
            const int v = g_hist[b];
            g_off[b]  = excl;
            g_hist[b] = 0;                      // clean for next graph replay
            excl += v;
        }
    }

    grid_barrier();

    // ---- Phase 3: atomic-free scatter ----
    for (int qi = gtid; qi < M; qi += T) {
        const int v = g_vidx[qi];
        const int r = g_rank[qi];
        const int bin = (v >= 0) ? (v >> BUCKET_SHIFT) : (NBINS - 1);
        g_perm[__ldg(&g_off[bin]) + r] = qi;
    }

    grid_barrier();

    // ---- Phase 4: persistent gather in sorted order ----
    const int lane  = tid & 31;
    const int gwarp = gtid >> 5;
    const int W     = T >> 5;                   // 4736 warps

    for (int wi = gwarp; wi < M; wi += W) {
        const int qi = __ldg(&g_perm[wi]);      // L2-resident, warp-broadcast
        const int v  = __ldg(&g_vidx[qi]);

        const float4* src = voxel_features + (size_t)v * VEC4_PER_ROW + lane;
        float4*       dst = out            + (size_t)qi * VEC4_PER_ROW + lane;

        float4 r[V4_PER_LANE];
        if (v >= 0) {
            #pragma unroll
            for (int i = 0; i < V4_PER_LANE; i++)   // 6 loads in flight
                r[i] = __ldg(src + 32 * i);
        } else {
            #pragma unroll
            for (int i = 0; i < V4_PER_LANE; i++)
                r[i] = make_float4(0.f, 0.f, 0.f, 0.f);
        }

        // Streaming stores: output never re-read; keep L2 for feature rows.
        #pragma unroll
        for (int i = 0; i < V4_PER_LANE; i++)
            __stcs(dst + 32 * i, r[i]);
    }
}

extern "C" void kernel_launch(void* const* d_in, const int* in_sizes, int n_in,
                              void* d_out, int out_size)
{
    const float*  query_pts = (const float*)d_in[0];
    const float4* feats     = (const float4*)d_in[1];
    const int*    buf       = (const int*)d_in[2];
    float4*       out       = (float4*)d_out;

    const int M = in_sizes[0] / 3;                  // 262144
    const int total_voxels = in_sizes[1] / FEATURE_DIM;

    voxel_fused<<<NBLOCKS, NTHREADS>>>(query_pts, feats, buf, out, M, total_voxels);
}

// round 10
// speedup vs baseline: 1.2459x; 1.2459x over previous
#include <cuda_runtime.h>
#include <cstdint>

// VoxelHashTable — hybrid: fused persistent pre-pass + standalone gather.
//
// R9 lesson: fusing the gather into a 592-block persistent kernel capped it
// at 32 warps/SM -> HBM fell to 4.4TB/s (needs ~53 warps/SM to saturate).
// R8 lesson: the three tiny pre-pass kernels cost ~31us of launch overhead
// for <8us of work.
// Fix: ONE persistent pre-pass kernel (hash -> scan -> scatter with grid
// barriers; latency-tolerant, residency-safe at 4 blocks/SM) + the proven
// full-occupancy gather launch. 2 launches total.

#define FEATURE_DIM 768
#define VEC4_PER_ROW (FEATURE_DIM / 4)     // 192
#define V4_PER_LANE (VEC4_PER_ROW / 32)    // 6
#define TABLE_MASK ((1u << 20) - 1u)
#define M_MAX (1 << 18)                    // 262144 queries
#define BUCKET_SHIFT 7                     // 128 voxel rows per bucket
#define NBINS 8192
#define PRE_BLOCKS 592                     // 4 * 148 (co-resident on 148/152 SM)
#define NTHREADS 256

__device__ int g_vidx[M_MAX];
__device__ int g_rank[M_MAX];
__device__ int g_perm[M_MAX];
__device__ int g_hist[NBINS];              // zero at load; scan re-zeroes
__device__ int g_off[NBINS];
__device__ unsigned g_bar_count;           // self-resetting
__device__ unsigned g_bar_gen;             // monotonic across replays

__device__ __forceinline__ void grid_barrier()
{
    __syncthreads();
    if (threadIdx.x == 0) {
        __threadfence();                       // publish this block's writes
        const unsigned gen = *(volatile unsigned*)&g_bar_gen;
        if (atomicAdd(&g_bar_count, 1) == gridDim.x - 1) {
            g_bar_count = 0;                   // reset BEFORE release
            __threadfence();
            *(volatile unsigned*)&g_bar_gen = gen + 1;   // release
        } else {
            while (*(volatile unsigned*)&g_bar_gen == gen)
                __nanosleep(64);
        }
        __threadfence();                       // acquire
    }
    __syncthreads();
}

__global__ void __launch_bounds__(NTHREADS, 4) prepass_fused(
    const float* __restrict__ query_pts,   // [M, 3]
    const int* __restrict__ buf,           // [2^20], int32
    int M, int total_voxels)
{
    const int tid  = threadIdx.x;
    const int gtid = blockIdx.x * NTHREADS + tid;
    const int T    = gridDim.x * NTHREADS;   // 151552 threads

    // ---- Phase 1: hash + table lookup + bin rank (atomicAdd return) ----
    for (int qi = gtid; qi < M; qi += T) {
        const float px = __ldg(&query_pts[qi * 3 + 0]);
        const float py = __ldg(&query_pts[qi * 3 + 1]);
        const float pz = __ldg(&query_pts[qi * 3 + 2]);

        // f32 division by 0.1f required for bit-exact floor(q / RES).
        const long long gx = (long long)floorf(px / 0.1f);
        const long long gy = (long long)floorf(py / 0.1f);
        const long long gz = (long long)floorf(pz / 0.1f);

        // Products ~1e10 overflow int32 -> 64-bit. Pow2 mod == AND (neg-safe).
        const unsigned h = (unsigned)((gx * 73856093LL + gy * 19349669LL
                                       + gz * 83492791LL) & (long long)TABLE_MASK);

        int v = __ldg(&buf[h]);
        if (v >= total_voxels) v = -1;

        const int bin = (v >= 0) ? (v >> BUCKET_SHIFT) : (NBINS - 1);
        g_vidx[qi] = v;
        g_rank[qi] = atomicAdd(&g_hist[bin], 1);
    }

    grid_barrier();

    // ---- Phase 2: exclusive scan of 8192 bins (block 0); re-zero hist ----
    if (blockIdx.x == 0) {
        constexpr int BPT = NBINS / NTHREADS;   // 32 bins/thread
        const int lane = tid & 31, warp = tid >> 5;

        int sum = 0;
        #pragma unroll 8
        for (int i = 0; i < BPT; i++)
            sum += g_hist[tid * BPT + i];

        int x = sum;                            // inclusive warp scan
        #pragma unroll
        for (int d = 1; d < 32; d <<= 1) {
            int y = __shfl_up_sync(0xFFFFFFFFu, x, d);
            if (lane >= d) x += y;
        }

        __shared__ int ws[NTHREADS / 32];
        if (lane == 31) ws[warp] = x;
        __syncthreads();
        if (tid == 0) {
            int a = 0;
            #pragma unroll
            for (int j = 0; j < NTHREADS / 32; j++) {
                int t = ws[j]; ws[j] = a; a += t;
            }
        }
        __syncthreads();

        int excl = x - sum + ws[warp];
        #pragma unroll 8
        for (int i = 0; i < BPT; i++) {
            const int b = tid * BPT + i;
            const int v = g_hist[b];
            g_off[b]  = excl;
            g_hist[b] = 0;                      // clean for next graph replay
            excl += v;
        }
    }

    grid_barrier();

    // ---- Phase 3: atomic-free scatter ----
    for (int qi = gtid; qi < M; qi += T) {
        const int v = g_vidx[qi];
        const int r = g_rank[qi];
        const int bin = (v >= 0) ? (v >> BUCKET_SHIFT) : (NBINS - 1);
        g_perm[__ldg(&g_off[bin]) + r] = qi;
    }
}

// Full-occupancy gather (unchanged from R8: 183-185us, at its byte floor).
__global__ void __launch_bounds__(NTHREADS) gather_phase(
    const float4* __restrict__ voxel_features,  // [total_voxels, 192] as float4
    float4* __restrict__ out)                   // [M, 192] as float4
{
    const int warp = threadIdx.x >> 5;
    const int lane = threadIdx.x & 31;
    const int wi   = blockIdx.x * (NTHREADS / 32) + warp;

    const int qi = __ldg(&g_perm[wi]);   // L2-resident, warp-broadcast
    const int v  = __ldg(&g_vidx[qi]);

    const float4* src = voxel_features + (size_t)v * VEC4_PER_ROW + lane;
    float4*       dst = out            + (size_t)qi * VEC4_PER_ROW + lane;

    float4 r[V4_PER_LANE];
    if (v >= 0) {
        #pragma unroll
        for (int i = 0; i < V4_PER_LANE; i++)   // 6 loads in flight (MLP=6)
            r[i] = __ldg(src + 32 * i);
    } else {
        #pragma unroll
        for (int i = 0; i < V4_PER_LANE; i++)
            r[i] = make_float4(0.f, 0.f, 0.f, 0.f);
    }

    // Streaming stores: output never re-read; keep L2 for feature rows.
    #pragma unroll
    for (int i = 0; i < V4_PER_LANE; i++)
        __stcs(dst + 32 * i, r[i]);
}

extern "C" void kernel_launch(void* const* d_in, const int* in_sizes, int n_in,
                              void* d_out, int out_size)
{
    const float*  query_pts = (const float*)d_in[0];
    const float4* feats     = (const float4*)d_in[1];
    const int*    buf       = (const int*)d_in[2];
    float4*       out       = (float4*)d_out;

    const int M = in_sizes[0] / 3;                  // 262144
    const int total_voxels = in_sizes[1] / FEATURE_DIM;

    prepass_fused<<<PRE_BLOCKS, NTHREADS>>>(query_pts, buf, M, total_voxels);
    gather_phase<<<M / (NTHREADS / 32), NTHREADS>>>(feats, out);
}

// round 12
// speedup vs baseline: 1.3352x; 1.0717x over previous
#include <cuda_runtime.h>
#include <cstdint>

// VoxelHashTable — counting-sort-clustered gather + PDL-overlapped launches.
//
// R8: gather at byte-floor (184us @ 6.5TB/s); pre-pass work <10us but 3 extra
//     launches cost ~31us total.
// R9/R10: persistent-kernel fusion FAILED (grid barriers + occupancy loss).
// This round: keep the 4-kernel dependency chain, hide the launch gaps with
// Programmatic Dependent Launch: downstream kernels launch with the
// ProgrammaticStreamSerialization attribute and self-gate via
// cudaGridDependencySynchronize(); producers trigger after their last write.
// Cross-replay: hash_hist is a NORMAL launch -> serializes against the
// previous replay's gather before scratch is overwritten.
//
// Also: scatter writes packed int2{qi, vidx} so gather needs one load, not
// perm -> dependent vidx (one fewer L2 round-trip on the critical chain).

#define FEATURE_DIM 768
#define VEC4_PER_ROW (FEATURE_DIM / 4)     // 192
#define V4_PER_LANE (VEC4_PER_ROW / 32)    // 6
#define TABLE_MASK ((1u << 20) - 1u)
#define THREADS 256
#define M_MAX (1 << 18)                    // 262144 queries
#define BUCKET_SHIFT 7                     // 128 voxel rows per bucket
#define NBINS 8192

__device__ int  g_vidx[M_MAX];
__device__ int  g_rank[M_MAX];
__device__ int2 g_sorted[M_MAX];           // {qi, vidx} in bin-sorted order
__device__ int  g_hist[NBINS];             // zero-init at load; scan re-zeroes
__device__ int  g_off[NBINS];

// 1 query/thread: hash, table lookup, bin rank via atomicAdd return.
__global__ void __launch_bounds__(256) hash_hist(
    const float* __restrict__ query_pts,   // [M, 3]
    const int* __restrict__ buf,           // [2^20], int32
    int total_voxels)
{
    const int qi = blockIdx.x * blockDim.x + threadIdx.x;

    const float px = __ldg(&query_pts[qi * 3 + 0]);
    const float py = __ldg(&query_pts[qi * 3 + 1]);
    const float pz = __ldg(&query_pts[qi * 3 + 2]);

    // f32 division by 0.1f required for bit-exact floor(q / RES).
    const long long gx = (long long)floorf(px / 0.1f);
    const long long gy = (long long)floorf(py / 0.1f);
    const long long gz = (long long)floorf(pz / 0.1f);

    // Products ~1e10 overflow int32 -> 64-bit. Pow2 mod == AND (neg-safe).
    const unsigned h = (unsigned)((gx * 73856093LL + gy * 19349669LL
                                   + gz * 83492791LL) & (long long)TABLE_MASK);

    int v = __ldg(&buf[h]);
    if (v >= total_voxels) v = -1;

    const int bin = (v >= 0) ? (v >> BUCKET_SHIFT) : (NBINS - 1);
    g_vidx[qi] = v;
    g_rank[qi] = atomicAdd(&g_hist[bin], 1);   // rank within bin

    cudaTriggerProgrammaticLaunchCompletion();
}

// Exclusive prefix sum over NBINS=8192 bins -> g_off. Single 1024-thread
// block. Also re-zeroes g_hist so the next graph replay starts clean.
__global__ void __launch_bounds__(1024) scan_hist()
{
    cudaGridDependencySynchronize();       // wait for hash_hist's writes

    const int tid  = threadIdx.x;
    const int lane = tid & 31;
    const int warp = tid >> 5;

    int v[NBINS / 1024];
    int sum = 0;
    #pragma unroll
    for (int i = 0; i < NBINS / 1024; i++) {
        v[i] = g_hist[tid * (NBINS / 1024) + i];
        g_hist[tid * (NBINS / 1024) + i] = 0;   // reset for next replay
        sum += v[i];
    }

    int x = sum;
    #pragma unroll
    for (int d = 1; d < 32; d <<= 1) {
        int y = __shfl_up_sync(0xFFFFFFFFu, x, d);
        if (lane >= d) x += y;
    }

    __shared__ int wsum[32];
    if (lane == 31) wsum[warp] = x;
    __syncthreads();
    if (warp == 0) {
        int w = wsum[lane];
        #pragma unroll
        for (int d = 1; d < 32; d <<= 1) {
            int y = __shfl_up_sync(0xFFFFFFFFu, w, d);
            if (lane >= d) w += y;
        }
        wsum[lane] = w;
    }
    __syncthreads();

    int excl = x - sum + (warp > 0 ? wsum[warp - 1] : 0);
    #pragma unroll
    for (int i = 0; i < NBINS / 1024; i++) {
        g_off[tid * (NBINS / 1024) + i] = excl;
        excl += v[i];
    }

    cudaTriggerProgrammaticLaunchCompletion();
}

// Atomic-free scatter: pos = off[bin] + rank; writes packed {qi, vidx}.
__global__ void __launch_bounds__(256) scatter_perm()
{
    cudaGridDependencySynchronize();       // wait for scan_hist's writes

    const int qi = blockIdx.x * blockDim.x + threadIdx.x;

    const int v = g_vidx[qi];
    const int r = g_rank[qi];
    const int bin = (v >= 0) ? (v >> BUCKET_SHIFT) : (NBINS - 1);
    const int pos = __ldg(&g_off[bin]) + r;   // off[] is L2-resident
    g_sorted[pos] = make_int2(qi, v);

    cudaTriggerProgrammaticLaunchCompletion();
}

// Full-occupancy gather: warp-per-row, 6 independent float4 loads, __stcs.
__global__ void __launch_bounds__(THREADS) gather_phase(
    const float4* __restrict__ voxel_features,  // [total_voxels, 192] as float4
    float4* __restrict__ out)                   // [M, 192] as float4
{
    cudaGridDependencySynchronize();       // wait for scatter's writes

    const int warp = threadIdx.x >> 5;
    const int lane = threadIdx.x & 31;
    const int wi   = blockIdx.x * (THREADS / 32) + warp;

    const int2 s = __ldg(&g_sorted[wi]);   // one load: {qi, vidx}
    const int qi = s.x;
    const int v  = s.y;

    const float4* src = voxel_features + (size_t)v * VEC4_PER_ROW + lane;
    float4*       dst = out            + (size_t)qi * VEC4_PER_ROW + lane;

    float4 r[V4_PER_LANE];
    if (v >= 0) {
        #pragma unroll
        for (int i = 0; i < V4_PER_LANE; i++)   // 6 loads in flight (MLP=6)
            r[i] = __ldg(src + 32 * i);
    } else {
        #pragma unroll
        for (int i = 0; i < V4_PER_LANE; i++)
            r[i] = make_float4(0.f, 0.f, 0.f, 0.f);
    }

    // Streaming stores: output never re-read; keep L2 for feature rows.
    #pragma unroll
    for (int i = 0; i < V4_PER_LANE; i++)
        __stcs(dst + 32 * i, r[i]);
}

// Launch helper: programmatic stream serialization (PDL) on downstream kernels.
template <typename... Args>
static void launch_pdl(void (*kernel)(Args...), dim3 grid, dim3 block, Args... args)
{
    cudaLaunchConfig_t cfg = {};
    cfg.gridDim  = grid;
    cfg.blockDim = block;
    cfg.dynamicSmemBytes = 0;
    cfg.stream = 0;
    cudaLaunchAttribute attr[1];
    attr[0].id = cudaLaunchAttributeProgrammaticStreamSerialization;
    attr[0].val.programmaticStreamSerializationAllowed = 1;
    cfg.attrs = attr;
    cfg.numAttrs = 1;
    cudaLaunchKernelEx(&cfg, kernel, args...);
}

extern "C" void kernel_launch(void* const* d_in, const int* in_sizes, int n_in,
                              void* d_out, int out_size)
{
    const float*  query_pts = (const float*)d_in[0];
    const float4* feats     = (const float4*)d_in[1];
    const int*    buf       = (const int*)d_in[2];
    float4*       out       = (float4*)d_out;

    const int M = in_sizes[0] / 3;                  // 262144
    const int total_voxels = in_sizes[1] / FEATURE_DIM;

    // hash_hist: NORMAL launch -> serializes against prior replay's gather
    // before scratch buffers are overwritten.
    hash_hist<<<M / 256, 256>>>(query_pts, buf, total_voxels);

    launch_pdl(scan_hist, dim3(1), dim3(1024));
    launch_pdl(scatter_perm, dim3(M / 256), dim3(256));
    launch_pdl(gather_phase, dim3(M / (THREADS / 32)), dim3(THREADS),
               feats, out);
}